// round 17
// baseline (speedup 1.0000x reference)
#include <cuda_runtime.h>
#include <cstdint>

#define DIM 4096
#define THREADS 128       // 4 warps; persistent CTAs, grid-stride over rows
#define NUM_SMS 148
#define CTAS_PER_SM 9     // matches measured residency of the 47-reg body

// padded smem address for element e: +4 words per 128 elements
#define SADDR(e) ((e) + 4 * ((e) >> 7))

__device__ __forceinline__ void bfly(float& a, float& b) {
    float s = a + b;
    float d = a - b;
    a = s; b = d;
}

__device__ __forceinline__ uint64_t policy_evict_last() {
    uint64_t pol;
    asm("createpolicy.fractional.L2::evict_last.b64 %0, 1.0;" : "=l"(pol));
    return pol;
}
__device__ __forceinline__ uint64_t policy_evict_first() {
    uint64_t pol;
    asm("createpolicy.fractional.L2::evict_first.b64 %0, 1.0;" : "=l"(pol));
    return pol;
}

// x is read-only and reused across graph replays: keep it resident in L2.
__device__ __forceinline__ float4 ldg_hint(const float4* p, uint64_t pol) {
    float4 f;
    asm volatile("ld.global.nc.L2::cache_hint.v4.f32 {%0,%1,%2,%3}, [%4], %5;"
                 : "=f"(f.x), "=f"(f.y), "=f"(f.z), "=f"(f.w)
                 : "l"(p), "l"(pol));
    return f;
}

// out is write-once streaming: evict promptly so it doesn't displace x.
__device__ __forceinline__ void stg_hint(float4* p, float4 f, uint64_t pol) {
    asm volatile("st.global.L2::cache_hint.v4.f32 [%0], {%1,%2,%3,%4}, %5;"
                 :: "l"(p), "f"(f.x), "f"(f.y), "f"(f.z), "f"(f.w), "l"(pol)
                 : "memory");
}

__global__ __launch_bounds__(THREADS)
void fwht4096_persist_kernel(const float* __restrict__ x,
                             float* __restrict__ out, int n_rows) {
    __shared__ float s[DIM + 4 * (DIM >> 7)];  // 4224 floats = 16896 B

    const int t = threadIdx.x;
    const uint64_t pol_ld = policy_evict_last();
    const uint64_t pol_st = policy_evict_first();

    bool first = true;
    for (int row = blockIdx.x; row < n_rows; row += gridDim.x) {
        const float4* __restrict__ xin =
            reinterpret_cast<const float4*>(x + (size_t)row * DIM);
        float4* __restrict__ oq =
            reinterpret_cast<float4*>(out + (size_t)row * DIM);

        // ================= Phase 1 =================
        // ownership: e = k_lo + 4*t + 512*k_hi (k_lo: e-bits 0-1, k_hi: 9-11)
        // reg k = 4*k_hi + k_lo -> reg bits map to e-bits {0,1,9,10,11}
        // Loads issue before the ex-reuse barrier: the next row's LDG burst
        // overlaps the tail of the previous row (persistent-CTA overlap).
        float v[32];
#pragma unroll
        for (int kh = 0; kh < 8; kh++) {
            float4 f = ldg_hint(xin + t + 128 * kh, pol_ld);  // 512B/warp
            v[4 * kh + 0] = f.x;
            v[4 * kh + 1] = f.y;
            v[4 * kh + 2] = f.z;
            v[4 * kh + 3] = f.w;
        }

        // butterfly e-bits {0,1,9,10,11} == all 5 register-index bits
#pragma unroll
        for (int h = 1; h <= 16; h <<= 1) {
#pragma unroll
            for (int k = 0; k < 32; k++) {
                if (!(k & h)) bfly(v[k], v[k ^ h]);
            }
        }

        // guard exchange-buffer reuse across loop iterations
        if (!first) __syncthreads();
        first = false;

        // write to smem at canonical padded addresses (float4 stores)
        {
            const int base = 4 * t + 4 * (t >> 5);  // SADDR(4t+512kh)=base+528kh
#pragma unroll
            for (int kh = 0; kh < 8; kh++) {
                *reinterpret_cast<float4*>(&s[base + 528 * kh]) =
                    make_float4(v[4 * kh + 0], v[4 * kh + 1],
                                v[4 * kh + 2], v[4 * kh + 3]);
            }
        }
        __syncthreads();

        // ================= Phase 2 =================
        // ownership: e = k_lo2 + 4*j + 128*m (j = e-bits 2-6 in registers)
        {
            float u[32];
            const int klo2 = t & 3;
            const int m = t >> 2;
            const int base2 = klo2 + 132 * m;  // SADDR(k_lo2+128m); +4j exact
#pragma unroll
            for (int j = 0; j < 32; j++) u[j] = s[base2 + 4 * j];

#pragma unroll
            for (int h = 1; h <= 16; h <<= 1) {
#pragma unroll
                for (int j = 0; j < 32; j++) {
                    if (!(j & h)) bfly(u[j], u[j ^ h]);
                }
            }

            // write back to the SAME addresses (thread-private this phase)
#pragma unroll
            for (int j = 0; j < 32; j++) s[base2 + 4 * j] = u[j];
        }
        __syncthreads();

        // ================= Phase 3 =================
        // ownership: e = k_lo3 + 4*l + 128*km + 1024*w3 ;
        // reg bits = e-bits {0,1,7,8,9}; butterfly e-bits {7,8}
        {
            float w[32];
            const int l = t & 31;
            const int w3 = t >> 5;
            const int base3 = 4 * l + 1056 * w3;  // SADDR(4l + 1024*w3)
#pragma unroll
            for (int km = 0; km < 8; km++) {
                float4 f = *reinterpret_cast<const float4*>(&s[base3 + 132 * km]);
                w[4 * km + 0] = f.x;
                w[4 * km + 1] = f.y;
                w[4 * km + 2] = f.z;
                w[4 * km + 3] = f.w;
            }

#pragma unroll
            for (int h = 4; h <= 8; h <<= 1) {
#pragma unroll
                for (int k = 0; k < 32; k++) {
                    if (!(k & h)) bfly(w[k], w[k ^ h]);
                }
            }

            // fully coalesced float4 stores: float4 index = l + 32*km + 256*w3
#pragma unroll
            for (int km = 0; km < 8; km++) {
                stg_hint(oq + l + 32 * km + 256 * w3,
                         make_float4(w[4 * km + 0], w[4 * km + 1],
                                     w[4 * km + 2], w[4 * km + 3]),
                         pol_st);
            }
        }
        // no trailing barrier: next iteration's pre-P1-store barrier orders
        // this iteration's ex reads before the next row's ex writes.
    }
}

extern "C" void kernel_launch(void* const* d_in, const int* in_sizes, int n_in,
                              void* d_out, int out_size) {
    // x is the input whose element count equals out_size (N_TOKENS*DIM);
    // H is implicit in the transform and never read.
    const float* x = (const float*)d_in[0];
    for (int i = 0; i < n_in; i++) {
        if (in_sizes[i] == out_size) { x = (const float*)d_in[i]; break; }
    }
    float* out = (float*)d_out;
    const int n_rows = out_size / DIM;  // 8192
    const int grid = NUM_SMS * CTAS_PER_SM;  // 1332 persistent CTAs
    fwht4096_persist_kernel<<<grid, THREADS>>>(x, out, n_rows);
}